// round 12
// baseline (speedup 1.0000x reference)
#include <cuda_runtime.h>
#include <math.h>

#define BDIM 512
#define TDIM 512
#define IN0  64
#define HDIM 128
#define G3   384   // 3*H  (gate order r, z, n)

typedef unsigned long long u64;

// ---------------------------------------------------------------------------
// f32x2 packed helpers
// ---------------------------------------------------------------------------
__device__ __forceinline__ u64 pack2u(unsigned int lo, unsigned int hi) {
    u64 r; asm("mov.b64 %0, {%1, %2};" : "=l"(r) : "r"(lo), "r"(hi)); return r;
}
__device__ __forceinline__ u64 splat2(unsigned int v) {
    u64 r; asm("mov.b64 %0, {%1, %1};" : "=l"(r) : "r"(v)); return r;
}
__device__ __forceinline__ void fma2(u64& d, u64 a, u64 b) {
    asm("fma.rn.f32x2 %0, %1, %2, %0;" : "+l"(d) : "l"(a), "l"(b));
}
__device__ __forceinline__ float2 unpack2(u64 v) {
    unsigned int lo, hi;
    asm("mov.b64 {%0, %1}, %2;" : "=r"(lo), "=r"(hi) : "l"(v));
    float2 f; f.x = __uint_as_float(lo); f.y = __uint_as_float(hi); return f;
}
__device__ __forceinline__ float sigmoid_f(float x) {
    return __fdividef(1.f, 1.f + __expf(-x));
}
__device__ __forceinline__ float tanh_f(float x) {
    // 2*sigmoid(2x) - 1 : short MUFU chain, rel err ~1e-6 (validated)
    return __fmaf_rn(2.f, __fdividef(1.f, 1.f + __expf(-2.f * x)), -1.f);
}

// ---------------------------------------------------------------------------
// Scratch
// ---------------------------------------------------------------------------
__device__ float g_gi [(size_t)BDIM * TDIM * G3];
__device__ float g_h1 [(size_t)BDIM * TDIM * HDIM];
__device__ float g_hlast[(size_t)BDIM * HDIM];
__device__ float g_WT0[64  * G3];    // W_ih0 transposed: [K][384]
__device__ float g_WT1[128 * G3];    // W_ih1 transposed: [K][384]

// ---------------------------------------------------------------------------
// One-time W_ih transpose: WT[k][g] = W[g][k].
// ---------------------------------------------------------------------------
template <int K>
__global__ void transpose_w(const float* __restrict__ W, float* __restrict__ WT)
{
    int idx = blockIdx.x * blockDim.x + threadIdx.x;
    if (idx >= G3 * K) return;
    int g = idx / K, k = idx - g * K;
    WT[k * G3 + g] = W[idx];
}

// ---------------------------------------------------------------------------
// gi GEMM (R9-exact, best measured): out[M,384] = X[M,K] @ W[384,K]^T + bias.
// ---------------------------------------------------------------------------
template <int K>
__global__ __launch_bounds__(256)
void gi_gemm(const float* __restrict__ X,
             const float* __restrict__ WT,   // [K][384] transposed
             const float* __restrict__ bias)
{
    constexpr int TM  = 64;
    constexpr int NC  = 96;
    constexpr int XP  = K + 4;
    constexpr int WP2 = 100;

    extern __shared__ float sm[];
    float* xs = sm;               // [TM][XP] row-major
    float* ws = sm + TM * XP;     // [K][WP2]; reused as [64][96] staging

    const int tid = threadIdx.x;
    const int rowbase = blockIdx.x * TM;

    for (int idx = tid; idx < TM * (K / 4); idx += 256) {
        int r = idx / (K / 4), kb = idx - r * (K / 4);
        float4 v = *(const float4*)&X[(size_t)(rowbase + r) * K + kb * 4];
        *(float4*)&xs[r * XP + kb * 4] = v;
    }

    const int rg = tid >> 4;
    const int gg = tid & 15;
    float* out = g_gi;

    for (int c = 0; c < 4; ++c) {
        __syncthreads();
        for (int idx = tid; idx < K * (NC / 4); idx += 256) {
            int k = idx / (NC / 4), g4 = idx - k * (NC / 4);
            float4 v = *(const float4*)&WT[(size_t)k * G3 + c * NC + g4 * 4];
            *(float4*)&ws[k * WP2 + g4 * 4] = v;
        }
        __syncthreads();

        u64 acc[4][3];
        #pragma unroll
        for (int i = 0; i < 4; ++i)
            #pragma unroll
            for (int p = 0; p < 3; ++p) acc[i][p] = 0ull;

        const float* xr0 = &xs[(rg * 4 + 0) * XP];
        const float* xr1 = &xs[(rg * 4 + 1) * XP];
        const float* xr2 = &xs[(rg * 4 + 2) * XP];
        const float* xr3 = &xs[(rg * 4 + 3) * XP];
        const float* wp0 = &ws[gg * 6];

        #pragma unroll 4
        for (int k = 0; k < K; ++k) {
            u64 x0 = splat2(__float_as_uint(xr0[k]));
            u64 x1 = splat2(__float_as_uint(xr1[k]));
            u64 x2 = splat2(__float_as_uint(xr2[k]));
            u64 x3 = splat2(__float_as_uint(xr3[k]));
            const u64* wrow = (const u64*)&wp0[k * WP2];
            u64 w01 = wrow[0], w23 = wrow[1], w45 = wrow[2];
            fma2(acc[0][0], x0, w01); fma2(acc[0][1], x0, w23); fma2(acc[0][2], x0, w45);
            fma2(acc[1][0], x1, w01); fma2(acc[1][1], x1, w23); fma2(acc[1][2], x1, w45);
            fma2(acc[2][0], x2, w01); fma2(acc[2][1], x2, w23); fma2(acc[2][2], x2, w45);
            fma2(acc[3][0], x3, w01); fma2(acc[3][1], x3, w23); fma2(acc[3][2], x3, w45);
        }

        __syncthreads();

        const int g0 = c * NC + gg * 6;
        #pragma unroll
        for (int p = 0; p < 3; ++p) {
            float b0 = bias[g0 + 2 * p];
            float b1 = bias[g0 + 2 * p + 1];
            #pragma unroll
            for (int i = 0; i < 4; ++i) {
                float2 v = unpack2(acc[i][p]);
                int r = rg * 4 + i;
                ws[r * NC + gg * 6 + 2 * p]     = v.x + b0;
                ws[r * NC + gg * 6 + 2 * p + 1] = v.y + b1;
            }
        }
        __syncthreads();

        #pragma unroll
        for (int v = 0; v < (TM * NC / 4) / 256; ++v) {
            int idx = (v * 256 + tid) * 4;
            int r = idx / NC, col = idx - r * NC;
            float4 val = *(const float4*)&ws[idx];
            *(float4*)&out[(size_t)(rowbase + r) * G3 + c * NC + col] = val;
        }
    }
}

// ---------------------------------------------------------------------------
// Persistent GRU recurrence v12: f32x2 lanes = (j, j+64) pairs.
// 512 thr: jg = tid&63 (j-pair), q = tid>>6 (k-eighth, warp-uniform).
// r/z weight PAIRS in regs (32 u64); n pairs via LDS.128 (2 k per load);
// h as LDS.128 per k, splatted per batch. LDS.128/thread/step: 40 -> 24.
// Reduction: 8 q-partials via smem (stride-13, conflict-free), 2 barriers.
// Gate thread (j=tid&127, b=tid>>7), h carried in register (v5-proven map).
// ---------------------------------------------------------------------------
template <int WRITE_SEQ>
__global__ __launch_bounds__(512, 1)
void gru_recurrent(const float* __restrict__ Whh,
                   const float* __restrict__ bhh)
{
    constexpr int PLANE = 128 * 13 + 1;   // 1665, q-plane pitch (odd)

    extern __shared__ float sm[];
    float* Wn2 = sm;                   // [8 kk2][512 tid][4]: (j0,j1)x(k,k+1)
    float* hs  = Wn2 + 8 * 512 * 4;    // [128][4], 16B-aligned
    float* red = hs + 512;             // [8][PLANE]

    const int tid = threadIdx.x;
    const int jg  = tid & 63;
    const int q   = tid >> 6;          // 0..7, uniform per warp
    const int b0  = blockIdx.x * 4;
    const int k0  = q * 16;

    // Stage n-gate weight pairs in consuming-tid order (one-time).
    for (int idx = tid; idx < 8 * 512 * 4; idx += 512) {
        int kk2 = idx >> 11;
        int rem = idx & 2047;
        int t2  = rem >> 2;
        int m   = rem & 3;
        int jg2 = t2 & 63, q2 = t2 >> 6;
        int k   = q2 * 16 + kk2 * 2 + (m >> 1);
        int jj  = (m & 1) ? (jg2 + 64) : jg2;
        Wn2[idx] = Whh[(size_t)(2 * HDIM + jj) * HDIM + k];
    }
    hs[tid] = 0.f;

    // r/z weight pairs (j, j+64) into registers.
    u64 wrp[16], wzp[16];
    #pragma unroll
    for (int kk = 0; kk < 16; ++kk) {
        int k = k0 + kk;
        wrp[kk] = pack2u(__float_as_uint(__ldg(Whh + (size_t)jg * HDIM + k)),
                         __float_as_uint(__ldg(Whh + (size_t)(jg + 64) * HDIM + k)));
        wzp[kk] = pack2u(__float_as_uint(__ldg(Whh + (size_t)(HDIM + jg) * HDIM + k)),
                         __float_as_uint(__ldg(Whh + (size_t)(HDIM + jg + 64) * HDIM + k)));
    }

    const int j = tid & 127;           // gate-phase identity
    const int b = tid >> 7;
    const float bhr = bhh[j];
    const float bhz = bhh[HDIM + j];
    const float bhn = bhh[2 * HDIM + j];

    __syncthreads();

    float* myred0 = red + q * PLANE + jg * 13;        // j = jg partials
    float* myred1 = myred0 + 64 * 13;                 // j = jg+64 partials
    const float* gi = g_gi + (size_t)(b0 + b) * TDIM * G3;
    const ulonglong2* h16  = (const ulonglong2*)hs;
    const ulonglong2* wn_l = (const ulonglong2*)Wn2 + tid;  // stride 512/kk2
    float hprev = 0.f;

    for (int t = 0; t < TDIM; ++t) {
        // Prefetch input-side preactivations (covered by the matvec).
        const float* gip = gi + (size_t)t * G3;
        float ir  = gip[j];
        float iz  = gip[HDIM + j];
        float in_ = gip[2 * HDIM + j];

        // acc[gate][batch], f32x2 lanes = (j, j+64)
        u64 ar0 = 0, ar1 = 0, ar2 = 0, ar3 = 0;
        u64 az0 = 0, az1 = 0, az2 = 0, az3 = 0;
        u64 an0 = 0, an1 = 0, an2 = 0, an3 = 0;

        #pragma unroll
        for (int kk2 = 0; kk2 < 8; ++kk2) {
            ulonglong2 wnp = wn_l[kk2 * 512];          // n pairs for k, k+1
            #pragma unroll
            for (int e = 0; e < 2; ++e) {
                int kk = kk2 * 2 + e;
                ulonglong2 hv = h16[k0 + kk];          // h[k][0..3]
                float2 h01 = unpack2(hv.x);
                float2 h23 = unpack2(hv.y);
                u64 hb0 = splat2(__float_as_uint(h01.x));
                u64 hb1 = splat2(__float_as_uint(h01.y));
                u64 hb2 = splat2(__float_as_uint(h23.x));
                u64 hb3 = splat2(__float_as_uint(h23.y));
                u64 wr = wrp[kk], wz = wzp[kk];
                u64 wn = e ? wnp.y : wnp.x;
                fma2(ar0, wr, hb0); fma2(ar1, wr, hb1);
                fma2(ar2, wr, hb2); fma2(ar3, wr, hb3);
                fma2(az0, wz, hb0); fma2(az1, wz, hb1);
                fma2(az2, wz, hb2); fma2(az3, wz, hb3);
                fma2(an0, wn, hb0); fma2(an1, wn, hb1);
                fma2(an2, wn, hb2); fma2(an3, wn, hb3);
            }
        }

        // Scatter partials: lane0 -> j=jg, lane1 -> j=jg+64. Index = g*4+b.
        {
            float2 v;
            v = unpack2(ar0); myred0[0]  = v.x; myred1[0]  = v.y;
            v = unpack2(ar1); myred0[1]  = v.x; myred1[1]  = v.y;
            v = unpack2(ar2); myred0[2]  = v.x; myred1[2]  = v.y;
            v = unpack2(ar3); myred0[3]  = v.x; myred1[3]  = v.y;
            v = unpack2(az0); myred0[4]  = v.x; myred1[4]  = v.y;
            v = unpack2(az1); myred0[5]  = v.x; myred1[5]  = v.y;
            v = unpack2(az2); myred0[6]  = v.x; myred1[6]  = v.y;
            v = unpack2(az3); myred0[7]  = v.x; myred1[7]  = v.y;
            v = unpack2(an0); myred0[8]  = v.x; myred1[8]  = v.y;
            v = unpack2(an1); myred0[9]  = v.x; myred1[9]  = v.y;
            v = unpack2(an2); myred0[10] = v.x; myred1[10] = v.y;
            v = unpack2(an3); myred0[11] = v.x; myred1[11] = v.y;
        }
        __syncthreads();

        // Gate phase: thread (j, b) sums 8 q-partials per gate.
        float sr = 0.f, sz = 0.f, sn = 0.f;
        #pragma unroll
        for (int qq = 0; qq < 8; ++qq) {
            const float* rp = red + qq * PLANE + j * 13;
            sr += rp[b];
            sz += rp[4 + b];
            sn += rp[8 + b];
        }
        float r = sigmoid_f(ir + sr + bhr);
        float z = sigmoid_f(iz + sz + bhz);
        float n = tanh_f(in_ + r * (sn + bhn));
        float hnew = n + z * (hprev - n);
        hprev = hnew;

        hs[j * 4 + b] = hnew;
        if (WRITE_SEQ) {
            g_h1[((size_t)(b0 + b) * TDIM + t) * HDIM + j] = hnew;  // coalesced
        } else if (t == TDIM - 1) {
            g_hlast[(size_t)(b0 + b) * HDIM + j] = hnew;
        }
        __syncthreads();
    }
}

// ---------------------------------------------------------------------------
// Final FC (O = 1): one warp per batch.
// ---------------------------------------------------------------------------
__global__ void fc_kernel(const float* __restrict__ Wfc,
                          const float* __restrict__ bfc,
                          float* __restrict__ out)
{
    int w = (blockIdx.x * blockDim.x + threadIdx.x) >> 5;
    int lane = threadIdx.x & 31;
    if (w >= BDIM) return;
    const float* hp = g_hlast + (size_t)w * HDIM;
    float s = 0.f;
    #pragma unroll
    for (int k = lane; k < HDIM; k += 32) s += hp[k] * Wfc[k];
    #pragma unroll
    for (int o = 16; o; o >>= 1) s += __shfl_xor_sync(0xFFFFFFFFu, s, o);
    if (lane == 0) out[w] = s + bfc[0];
}

// ---------------------------------------------------------------------------
extern "C" void kernel_launch(void* const* d_in, const int* in_sizes, int n_in,
                              void* d_out, int out_size)
{
    const float* x     = (const float*)d_in[0];
    const float* W_ih0 = (const float*)d_in[1];
    const float* W_hh0 = (const float*)d_in[2];
    const float* b_ih0 = (const float*)d_in[3];
    const float* b_hh0 = (const float*)d_in[4];
    const float* W_ih1 = (const float*)d_in[5];
    const float* W_hh1 = (const float*)d_in[6];
    const float* b_ih1 = (const float*)d_in[7];
    const float* b_hh1 = (const float*)d_in[8];
    const float* W_fc  = (const float*)d_in[9];
    const float* b_fc  = (const float*)d_in[10];
    float* out = (float*)d_out;

    const int SMEM_G64  = (64 * 68  + 64  * 100) * 4;   // 43,008 B
    const int SMEM_G128 = (64 * 132 + 128 * 100) * 4;   // 85,504 B
    const int SMEM_REC  = (8 * 512 * 4 + 512 + 8 * (128 * 13 + 1)) * 4; // 120,864 B

    cudaFuncSetAttribute(gi_gemm<64>,  cudaFuncAttributeMaxDynamicSharedMemorySize, SMEM_G64);
    cudaFuncSetAttribute(gi_gemm<128>, cudaFuncAttributeMaxDynamicSharedMemorySize, SMEM_G128);
    cudaFuncSetAttribute(gru_recurrent<1>, cudaFuncAttributeMaxDynamicSharedMemorySize, SMEM_REC);
    cudaFuncSetAttribute(gru_recurrent<0>, cudaFuncAttributeMaxDynamicSharedMemorySize, SMEM_REC);

    void* h1ptr = nullptr;
    cudaGetSymbolAddress(&h1ptr, g_h1);
    void* wt0ptr = nullptr;
    cudaGetSymbolAddress(&wt0ptr, g_WT0);
    void* wt1ptr = nullptr;
    cudaGetSymbolAddress(&wt1ptr, g_WT1);

    const int M = BDIM * TDIM;
    const int GEMM_GRID = M / 64;

    transpose_w<64> <<<(G3 * 64  + 255) / 256, 256>>>(W_ih0, (float*)wt0ptr);
    transpose_w<128><<<(G3 * 128 + 255) / 256, 256>>>(W_ih1, (float*)wt1ptr);

    gi_gemm<64><<<GEMM_GRID, 256, SMEM_G64>>>(x, (const float*)wt0ptr, b_ih0);
    gru_recurrent<1><<<BDIM / 4, 512, SMEM_REC>>>(W_hh0, b_hh0);
    gi_gemm<128><<<GEMM_GRID, 256, SMEM_G128>>>((const float*)h1ptr, (const float*)wt1ptr, b_ih1);
    gru_recurrent<0><<<BDIM / 4, 512, SMEM_REC>>>(W_hh1, b_hh1);
    fc_kernel<<<BDIM / 4, 128>>>(W_fc, b_fc, out);
}

// round 13
// speedup vs baseline: 1.0435x; 1.0435x over previous
#include <cuda_runtime.h>
#include <math.h>

#define BDIM 512
#define TDIM 512
#define IN0  64
#define HDIM 128
#define G3   384   // 3*H  (gate order r, z, n)

typedef unsigned long long u64;

// ---------------------------------------------------------------------------
// f32x2 packed helpers
// ---------------------------------------------------------------------------
__device__ __forceinline__ u64 splat2(unsigned int v) {
    u64 r; asm("mov.b64 %0, {%1, %1};" : "=l"(r) : "r"(v)); return r;
}
__device__ __forceinline__ void fma2(u64& d, u64 a, u64 b) {
    asm("fma.rn.f32x2 %0, %1, %2, %0;" : "+l"(d) : "l"(a), "l"(b));
}
__device__ __forceinline__ float2 unpack2(u64 v) {
    unsigned int lo, hi;
    asm("mov.b64 {%0, %1}, %2;" : "=r"(lo), "=r"(hi) : "l"(v));
    float2 f; f.x = __uint_as_float(lo); f.y = __uint_as_float(hi); return f;
}
__device__ __forceinline__ float sigmoid_f(float x) {
    return __fdividef(1.f, 1.f + __expf(-x));
}
__device__ __forceinline__ float tanh_f(float x) {
    // 2*sigmoid(2x) - 1 : short MUFU chain, rel err ~1e-6 (validated)
    return __fmaf_rn(2.f, __fdividef(1.f, 1.f + __expf(-2.f * x)), -1.f);
}

// ---------------------------------------------------------------------------
// Scratch
// ---------------------------------------------------------------------------
__device__ float g_gi [(size_t)BDIM * TDIM * G3];
__device__ float g_h1 [(size_t)BDIM * TDIM * HDIM];
__device__ float g_hlast[(size_t)BDIM * HDIM];
__device__ float g_WT0[64  * G3];    // W_ih0 transposed: [K][384]
__device__ float g_WT1[128 * G3];    // W_ih1 transposed: [K][384]

// ---------------------------------------------------------------------------
// One-time W_ih transpose: WT[k][g] = W[g][k].
// ---------------------------------------------------------------------------
template <int K>
__global__ void transpose_w(const float* __restrict__ W, float* __restrict__ WT)
{
    int idx = blockIdx.x * blockDim.x + threadIdx.x;
    if (idx >= G3 * K) return;
    int g = idx / K, k = idx - g * K;
    WT[k * G3 + g] = W[idx];
}

// ---------------------------------------------------------------------------
// gi GEMM v13: v9 + duplicated-x smem (kills 4 splats/k: 23 -> 19 issues
// per 12 FFMA2, flipping the kernel from issue-bound to fma-bound) +
// 64-wide k-tiling so smem stays at 59 KB -> 3 CTAs/SM for both K.
// Inner loop per k: 4 LDS.64 (x dup) + 3 LDS.64 (w) + 12 FFMA2.
// ---------------------------------------------------------------------------
template <int K>
__global__ __launch_bounds__(256)
void gi_gemm(const float* __restrict__ X,
             const float* __restrict__ WT,   // [K][384] transposed
             const float* __restrict__ bias)
{
    constexpr int TM  = 64;
    constexpr int NC  = 96;
    constexpr int KT  = 64;          // k-tile
    constexpr int NH  = K / KT;      // 1 or 2 halves
    constexpr int XP2 = 2 * KT + 4;  // 132: duplicated-pair row pitch
    constexpr int WP2 = 100;

    extern __shared__ float sm[];
    float* xs = sm;                  // [TM][XP2]  xs[r][2k]=xs[r][2k+1]=x
    float* ws = sm + TM * XP2;       // [KT][WP2]; reused as [64][96] staging

    const int tid = threadIdx.x;
    const int rowbase = blockIdx.x * TM;
    const int rg = tid >> 4;         // 0..15 : row group (4 rows)
    const int gg = tid & 15;         // 0..15 : gate group (6 gates)
    float* out = g_gi;

    for (int c = 0; c < 4; ++c) {
        u64 acc[4][3];
        #pragma unroll
        for (int i = 0; i < 4; ++i)
            #pragma unroll
            for (int p = 0; p < 3; ++p) acc[i][p] = 0ull;

        for (int hh = 0; hh < NH; ++hh) {
            __syncthreads();   // previous readers of xs/ws are done

            // Stage X half, duplicated: float4 in, 4x float2(v,v) out.
            for (int idx = tid; idx < TM * (KT / 4); idx += 256) {
                int r = idx / (KT / 4), kb = idx - r * (KT / 4);
                float4 v = *(const float4*)&X[(size_t)(rowbase + r) * K + hh * KT + kb * 4];
                float* xp = &xs[r * XP2 + kb * 8];
                *(float2*)&xp[0] = make_float2(v.x, v.x);
                *(float2*)&xp[2] = make_float2(v.y, v.y);
                *(float2*)&xp[4] = make_float2(v.z, v.z);
                *(float2*)&xp[6] = make_float2(v.w, v.w);
            }
            // Stage W chunk-half from transposed global: coalesced float4.
            for (int idx = tid; idx < KT * (NC / 4); idx += 256) {
                int k = idx / (NC / 4), g4 = idx - k * (NC / 4);
                float4 v = *(const float4*)&WT[(size_t)(hh * KT + k) * G3 + c * NC + g4 * 4];
                *(float4*)&ws[k * WP2 + g4 * 4] = v;
            }
            __syncthreads();

            const u64* xr0 = (const u64*)&xs[(rg * 4 + 0) * XP2];
            const u64* xr1 = (const u64*)&xs[(rg * 4 + 1) * XP2];
            const u64* xr2 = (const u64*)&xs[(rg * 4 + 2) * XP2];
            const u64* xr3 = (const u64*)&xs[(rg * 4 + 3) * XP2];
            const float* wp0 = &ws[gg * 6];

            #pragma unroll 4
            for (int k = 0; k < KT; ++k) {
                u64 x0 = xr0[k];                    // (x,x) pair, LDS.64
                u64 x1 = xr1[k];
                u64 x2 = xr2[k];
                u64 x3 = xr3[k];
                const u64* wrow = (const u64*)&wp0[k * WP2];
                u64 w01 = wrow[0], w23 = wrow[1], w45 = wrow[2];
                fma2(acc[0][0], x0, w01); fma2(acc[0][1], x0, w23); fma2(acc[0][2], x0, w45);
                fma2(acc[1][0], x1, w01); fma2(acc[1][1], x1, w23); fma2(acc[1][2], x1, w45);
                fma2(acc[2][0], x2, w01); fma2(acc[2][1], x2, w23); fma2(acc[2][2], x2, w45);
                fma2(acc[3][0], x3, w01); fma2(acc[3][1], x3, w23); fma2(acc[3][2], x3, w45);
            }
        }

        __syncthreads();  // done reading ws; reuse as output staging

        const int g0 = c * NC + gg * 6;
        #pragma unroll
        for (int p = 0; p < 3; ++p) {
            float b0 = bias[g0 + 2 * p];
            float b1 = bias[g0 + 2 * p + 1];
            #pragma unroll
            for (int i = 0; i < 4; ++i) {
                float2 v = unpack2(acc[i][p]);
                int r = rg * 4 + i;
                ws[r * NC + gg * 6 + 2 * p]     = v.x + b0;
                ws[r * NC + gg * 6 + 2 * p + 1] = v.y + b1;
            }
        }
        __syncthreads();

        #pragma unroll
        for (int v = 0; v < (TM * NC / 4) / 256; ++v) {
            int idx = (v * 256 + tid) * 4;
            int r = idx / NC, col = idx - r * NC;
            float4 val = *(const float4*)&ws[idx];
            *(float4*)&out[(size_t)(rowbase + r) * G3 + c * NC + col] = val;
        }
    }
}

// ---------------------------------------------------------------------------
// Persistent GRU recurrence (R9-exact, best measured: 672 us).
// 512 thr: j = tid&127 (hidden unit), q = tid>>7 (k-quarter, inter-warp).
// r/z weights in regs; n weights quad-LDS.128; h as LDS.128 broadcast per k.
// smem reduction (RP=13), 2 barriers/step.
// ---------------------------------------------------------------------------
template <int WRITE_SEQ>
__global__ __launch_bounds__(512, 1)
void gru_recurrent(const float* __restrict__ Whh,
                   const float* __restrict__ bhh)
{
    constexpr int RP = 13;

    extern __shared__ float sm[];
    float* Wn4 = sm;                     // [8][512][4] quad layout
    float* hs  = Wn4 + 8 * 512 * 4;      // [128][4], 16B-aligned
    float* red = hs + HDIM * 4;          // [4][128][RP]

    const int tid = threadIdx.x;
    const int j   = tid & 127;
    const int q   = tid >> 7;
    const int b0  = blockIdx.x * 4;
    const int k0  = q * 32;

    // Stage n-gate weights in consuming-tid quad order (one-time).
    for (int idx = tid; idx < 8 * 512 * 4; idx += 512) {
        int kkg = idx >> 11;
        int rem = idx & 2047;
        int t2  = rem >> 2;
        int m   = rem & 3;
        int j2  = t2 & 127, q2 = t2 >> 7;
        int k2  = q2 * 32 + kkg * 4 + m;
        Wn4[idx] = Whh[(size_t)(2 * HDIM + j2) * HDIM + k2];
    }
    hs[tid & 511] = 0.f;

    // r/z weights into registers (k = k0 + kk).
    unsigned int wrz[64];
    #pragma unroll
    for (int kk = 0; kk < 32; ++kk) {
        wrz[2 * kk]     = __float_as_uint(__ldg(Whh + (size_t)j * HDIM + k0 + kk));
        wrz[2 * kk + 1] = __float_as_uint(__ldg(Whh + (size_t)(HDIM + j) * HDIM + k0 + kk));
    }
    const float bhr = bhh[j];
    const float bhz = bhh[HDIM + j];
    const float bhn = bhh[2 * HDIM + j];

    __syncthreads();

    float* myred = &red[(q * HDIM + j) * RP];
    const float* gi = g_gi + (size_t)(b0 + q) * TDIM * G3;
    const ulonglong2* h16 = (const ulonglong2*)hs;     // one 16B broadcast per k
    const uint4* wn4p = (const uint4*)Wn4 + tid;       // stride 512 uint4 per kkg

    for (int t = 0; t < TDIM; ++t) {
        // Prefetch input-side preactivations (covered by the matvec).
        const float* gip = gi + (size_t)t * G3;
        float ir  = gip[j];
        float iz  = gip[HDIM + j];
        float in_ = gip[2 * HDIM + j];

        u64 a_r01 = 0, a_r23 = 0, a_z01 = 0, a_z23 = 0, a_n01 = 0, a_n23 = 0;

        #pragma unroll
        for (int kkg = 0; kkg < 8; ++kkg) {
            uint4 wq = wn4p[kkg * 512];                 // wn for 4 k, coalesced
            #pragma unroll
            for (int m = 0; m < 4; ++m) {
                int kk = kkg * 4 + m;
                ulonglong2 hv = h16[k0 + kk];           // LDS.128 broadcast
                u64 wr2 = splat2(wrz[2 * kk]);
                u64 wz2 = splat2(wrz[2 * kk + 1]);
                unsigned int wnu = (m == 0) ? wq.x : (m == 1) ? wq.y
                                 : (m == 2) ? wq.z : wq.w;
                u64 wn2 = splat2(wnu);
                fma2(a_r01, wr2, hv.x); fma2(a_r23, wr2, hv.y);
                fma2(a_z01, wz2, hv.x); fma2(a_z23, wz2, hv.y);
                fma2(a_n01, wn2, hv.x); fma2(a_n23, wn2, hv.y);
            }
        }

        {
            float2 v;
            v = unpack2(a_r01); myred[0]  = v.x; myred[1]  = v.y;
            v = unpack2(a_r23); myred[2]  = v.x; myred[3]  = v.y;
            v = unpack2(a_z01); myred[4]  = v.x; myred[5]  = v.y;
            v = unpack2(a_z23); myred[6]  = v.x; myred[7]  = v.y;
            v = unpack2(a_n01); myred[8]  = v.x; myred[9]  = v.y;
            v = unpack2(a_n23); myred[10] = v.x; myred[11] = v.y;
        }
        __syncthreads();

        // Gate phase: thread (j, q) finishes batch b = q.
        const int b = q;
        float sr = 0.f, sz = 0.f, sn = 0.f;
        #pragma unroll
        for (int qq = 0; qq < 4; ++qq) {
            const float* rp = &red[(qq * HDIM + j) * RP];
            sr += rp[0 * 4 + b];
            sz += rp[1 * 4 + b];
            sn += rp[2 * 4 + b];
        }
        float r = sigmoid_f(ir + sr + bhr);
        float z = sigmoid_f(iz + sz + bhz);
        float n = tanh_f(in_ + r * (sn + bhn));
        float hold = hs[j * 4 + b];
        float hnew = n + z * (hold - n);

        hs[j * 4 + b] = hnew;
        if (WRITE_SEQ) {
            g_h1[((size_t)(b0 + b) * TDIM + t) * HDIM + j] = hnew;  // coalesced
        } else if (t == TDIM - 1) {
            g_hlast[(size_t)(b0 + b) * HDIM + j] = hnew;
        }
        __syncthreads();
    }
}

// ---------------------------------------------------------------------------
// Final FC (O = 1): one warp per batch.
// ---------------------------------------------------------------------------
__global__ void fc_kernel(const float* __restrict__ Wfc,
                          const float* __restrict__ bfc,
                          float* __restrict__ out)
{
    int w = (blockIdx.x * blockDim.x + threadIdx.x) >> 5;
    int lane = threadIdx.x & 31;
    if (w >= BDIM) return;
    const float* hp = g_hlast + (size_t)w * HDIM;
    float s = 0.f;
    #pragma unroll
    for (int k = lane; k < HDIM; k += 32) s += hp[k] * Wfc[k];
    #pragma unroll
    for (int o = 16; o; o >>= 1) s += __shfl_xor_sync(0xFFFFFFFFu, s, o);
    if (lane == 0) out[w] = s + bfc[0];
}

// ---------------------------------------------------------------------------
extern "C" void kernel_launch(void* const* d_in, const int* in_sizes, int n_in,
                              void* d_out, int out_size)
{
    const float* x     = (const float*)d_in[0];
    const float* W_ih0 = (const float*)d_in[1];
    const float* W_hh0 = (const float*)d_in[2];
    const float* b_ih0 = (const float*)d_in[3];
    const float* b_hh0 = (const float*)d_in[4];
    const float* W_ih1 = (const float*)d_in[5];
    const float* W_hh1 = (const float*)d_in[6];
    const float* b_ih1 = (const float*)d_in[7];
    const float* b_hh1 = (const float*)d_in[8];
    const float* W_fc  = (const float*)d_in[9];
    const float* b_fc  = (const float*)d_in[10];
    float* out = (float*)d_out;

    // xs [64][132] + ws [64][100] = 59,392 B (both K; k-tiled at 64)
    const int SMEM_GEMM = (64 * 132 + 64 * 100) * 4;
    const int SMEM_REC  = (8 * 512 * 4 + HDIM * 4 + 4 * HDIM * 13) * 4; // 94,208 B

    cudaFuncSetAttribute(gi_gemm<64>,  cudaFuncAttributeMaxDynamicSharedMemorySize, SMEM_GEMM);
    cudaFuncSetAttribute(gi_gemm<128>, cudaFuncAttributeMaxDynamicSharedMemorySize, SMEM_GEMM);
    cudaFuncSetAttribute(gru_recurrent<1>, cudaFuncAttributeMaxDynamicSharedMemorySize, SMEM_REC);
    cudaFuncSetAttribute(gru_recurrent<0>, cudaFuncAttributeMaxDynamicSharedMemorySize, SMEM_REC);

    void* h1ptr = nullptr;
    cudaGetSymbolAddress(&h1ptr, g_h1);
    void* wt0ptr = nullptr;
    cudaGetSymbolAddress(&wt0ptr, g_WT0);
    void* wt1ptr = nullptr;
    cudaGetSymbolAddress(&wt1ptr, g_WT1);

    const int M = BDIM * TDIM;
    const int GEMM_GRID = M / 64;

    transpose_w<64> <<<(G3 * 64  + 255) / 256, 256>>>(W_ih0, (float*)wt0ptr);
    transpose_w<128><<<(G3 * 128 + 255) / 256, 256>>>(W_ih1, (float*)wt1ptr);

    gi_gemm<64><<<GEMM_GRID, 256, SMEM_GEMM>>>(x, (const float*)wt0ptr, b_ih0);
    gru_recurrent<1><<<BDIM / 4, 512, SMEM_REC>>>(W_hh0, b_hh0);
    gi_gemm<128><<<GEMM_GRID, 256, SMEM_GEMM>>>((const float*)h1ptr, (const float*)wt1ptr, b_ih1);
    gru_recurrent<0><<<BDIM / 4, 512, SMEM_REC>>>(W_hh1, b_hh1);
    fc_kernel<<<BDIM / 4, 128>>>(W_fc, b_fc, out);
}

// round 14
// speedup vs baseline: 1.1141x; 1.0677x over previous
#include <cuda_runtime.h>
#include <math.h>

#define BDIM 512
#define TDIM 512
#define IN0  64
#define HDIM 128
#define G3   384   // 3*H  (gate order r, z, n)

typedef unsigned long long u64;

// ---------------------------------------------------------------------------
// f32x2 packed helpers
// ---------------------------------------------------------------------------
__device__ __forceinline__ u64 splat2(unsigned int v) {
    u64 r; asm("mov.b64 %0, {%1, %1};" : "=l"(r) : "r"(v)); return r;
}
__device__ __forceinline__ void fma2(u64& d, u64 a, u64 b) {
    asm("fma.rn.f32x2 %0, %1, %2, %0;" : "+l"(d) : "l"(a), "l"(b));
}
__device__ __forceinline__ float2 unpack2(u64 v) {
    unsigned int lo, hi;
    asm("mov.b64 {%0, %1}, %2;" : "=r"(lo), "=r"(hi) : "l"(v));
    float2 f; f.x = __uint_as_float(lo); f.y = __uint_as_float(hi); return f;
}
__device__ __forceinline__ float sigmoid_f(float x) {
    return __fdividef(1.f, 1.f + __expf(-x));
}
__device__ __forceinline__ float tanh_f(float x) {
    // 2*sigmoid(2x) - 1 : short MUFU chain, rel err ~1e-6 (validated)
    return __fmaf_rn(2.f, __fdividef(1.f, 1.f + __expf(-2.f * x)), -1.f);
}

// ---------------------------------------------------------------------------
// Scratch
// ---------------------------------------------------------------------------
__device__ float g_gi [(size_t)BDIM * TDIM * G3];
__device__ float g_h1 [(size_t)BDIM * TDIM * HDIM];
__device__ float g_hlast[(size_t)BDIM * HDIM];
__device__ float g_WT0[64  * G3];    // W_ih0 transposed: [K][384]
__device__ float g_WT1[128 * G3];    // W_ih1 transposed: [K][384]

// ---------------------------------------------------------------------------
// One-time W_ih transpose: WT[k][g] = W[g][k].
// ---------------------------------------------------------------------------
template <int K>
__global__ void transpose_w(const float* __restrict__ W, float* __restrict__ WT)
{
    int idx = blockIdx.x * blockDim.x + threadIdx.x;
    if (idx >= G3 * K) return;
    int g = idx / K, k = idx - g * K;
    WT[k * G3 + g] = W[idx];
}

// ---------------------------------------------------------------------------
// gi GEMM K=64, duplicated-x variant: X staged ONCE duplicated
// (xs[r][2k]=xs[r][2k+1]=x), killing the 4 splats/k.
// Inner loop per k: 4 LDS.64 (x) + 3 LDS.64 (w) + 12 FFMA2 = 19 issues
// per 24 fma-cycles (v9 was 23). Staging/flush otherwise R9-exact.
// ---------------------------------------------------------------------------
__global__ __launch_bounds__(256)
void gi_gemm64_dup(const float* __restrict__ X,
                   const float* __restrict__ WT,   // [64][384] transposed
                   const float* __restrict__ bias)
{
    constexpr int K   = 64;
    constexpr int TM  = 64;
    constexpr int NC  = 96;
    constexpr int XP2 = 2 * K + 4;   // 132, duplicated-pair row pitch
    constexpr int WP2 = 100;

    extern __shared__ float sm[];
    float* xs = sm;                  // [TM][XP2]
    float* ws = sm + TM * XP2;       // [K][WP2]; reused as [64][96] staging

    const int tid = threadIdx.x;
    const int rowbase = blockIdx.x * TM;

    // Stage X duplicated: float4 in, 4x float2(v,v) out. Once.
    for (int idx = tid; idx < TM * (K / 4); idx += 256) {
        int r = idx / (K / 4), kb = idx - r * (K / 4);
        float4 v = *(const float4*)&X[(size_t)(rowbase + r) * K + kb * 4];
        float* xp = &xs[r * XP2 + kb * 8];
        *(float2*)&xp[0] = make_float2(v.x, v.x);
        *(float2*)&xp[2] = make_float2(v.y, v.y);
        *(float2*)&xp[4] = make_float2(v.z, v.z);
        *(float2*)&xp[6] = make_float2(v.w, v.w);
    }

    const int rg = tid >> 4;
    const int gg = tid & 15;
    float* out = g_gi;

    for (int c = 0; c < 4; ++c) {
        __syncthreads();
        for (int idx = tid; idx < K * (NC / 4); idx += 256) {
            int k = idx / (NC / 4), g4 = idx - k * (NC / 4);
            float4 v = *(const float4*)&WT[(size_t)k * G3 + c * NC + g4 * 4];
            *(float4*)&ws[k * WP2 + g4 * 4] = v;
        }
        __syncthreads();

        u64 acc[4][3];
        #pragma unroll
        for (int i = 0; i < 4; ++i)
            #pragma unroll
            for (int p = 0; p < 3; ++p) acc[i][p] = 0ull;

        const u64* xr0 = (const u64*)&xs[(rg * 4 + 0) * XP2];
        const u64* xr1 = (const u64*)&xs[(rg * 4 + 1) * XP2];
        const u64* xr2 = (const u64*)&xs[(rg * 4 + 2) * XP2];
        const u64* xr3 = (const u64*)&xs[(rg * 4 + 3) * XP2];
        const float* wp0 = &ws[gg * 6];

        #pragma unroll 4
        for (int k = 0; k < K; ++k) {
            u64 x0 = xr0[k];                    // (x,x) pair, LDS.64
            u64 x1 = xr1[k];
            u64 x2 = xr2[k];
            u64 x3 = xr3[k];
            const u64* wrow = (const u64*)&wp0[k * WP2];
            u64 w01 = wrow[0], w23 = wrow[1], w45 = wrow[2];
            fma2(acc[0][0], x0, w01); fma2(acc[0][1], x0, w23); fma2(acc[0][2], x0, w45);
            fma2(acc[1][0], x1, w01); fma2(acc[1][1], x1, w23); fma2(acc[1][2], x1, w45);
            fma2(acc[2][0], x2, w01); fma2(acc[2][1], x2, w23); fma2(acc[2][2], x2, w45);
            fma2(acc[3][0], x3, w01); fma2(acc[3][1], x3, w23); fma2(acc[3][2], x3, w45);
        }

        __syncthreads();  // done reading ws; reuse as output staging

        const int g0 = c * NC + gg * 6;
        #pragma unroll
        for (int p = 0; p < 3; ++p) {
            float b0 = bias[g0 + 2 * p];
            float b1 = bias[g0 + 2 * p + 1];
            #pragma unroll
            for (int i = 0; i < 4; ++i) {
                float2 v = unpack2(acc[i][p]);
                int r = rg * 4 + i;
                ws[r * NC + gg * 6 + 2 * p]     = v.x + b0;
                ws[r * NC + gg * 6 + 2 * p + 1] = v.y + b1;
            }
        }
        __syncthreads();

        #pragma unroll
        for (int v = 0; v < (TM * NC / 4) / 256; ++v) {
            int idx = (v * 256 + tid) * 4;
            int r = idx / NC, col = idx - r * NC;
            float4 val = *(const float4*)&ws[idx];
            *(float4*)&out[(size_t)(rowbase + r) * G3 + c * NC + col] = val;
        }
    }
}

// ---------------------------------------------------------------------------
// gi GEMM (R9-exact) for K=128: out[M,384] = X[M,K] @ W[384,K]^T + bias.
// ---------------------------------------------------------------------------
template <int K>
__global__ __launch_bounds__(256)
void gi_gemm(const float* __restrict__ X,
             const float* __restrict__ WT,   // [K][384] transposed
             const float* __restrict__ bias)
{
    constexpr int TM  = 64;
    constexpr int NC  = 96;
    constexpr int XP  = K + 4;
    constexpr int WP2 = 100;

    extern __shared__ float sm[];
    float* xs = sm;               // [TM][XP] row-major
    float* ws = sm + TM * XP;     // [K][WP2]; reused as [64][96] staging

    const int tid = threadIdx.x;
    const int rowbase = blockIdx.x * TM;

    for (int idx = tid; idx < TM * (K / 4); idx += 256) {
        int r = idx / (K / 4), kb = idx - r * (K / 4);
        float4 v = *(const float4*)&X[(size_t)(rowbase + r) * K + kb * 4];
        *(float4*)&xs[r * XP + kb * 4] = v;
    }

    const int rg = tid >> 4;
    const int gg = tid & 15;
    float* out = g_gi;

    for (int c = 0; c < 4; ++c) {
        __syncthreads();
        for (int idx = tid; idx < K * (NC / 4); idx += 256) {
            int k = idx / (NC / 4), g4 = idx - k * (NC / 4);
            float4 v = *(const float4*)&WT[(size_t)k * G3 + c * NC + g4 * 4];
            *(float4*)&ws[k * WP2 + g4 * 4] = v;
        }
        __syncthreads();

        u64 acc[4][3];
        #pragma unroll
        for (int i = 0; i < 4; ++i)
            #pragma unroll
            for (int p = 0; p < 3; ++p) acc[i][p] = 0ull;

        const float* xr0 = &xs[(rg * 4 + 0) * XP];
        const float* xr1 = &xs[(rg * 4 + 1) * XP];
        const float* xr2 = &xs[(rg * 4 + 2) * XP];
        const float* xr3 = &xs[(rg * 4 + 3) * XP];
        const float* wp0 = &ws[gg * 6];

        #pragma unroll 4
        for (int k = 0; k < K; ++k) {
            u64 x0 = splat2(__float_as_uint(xr0[k]));
            u64 x1 = splat2(__float_as_uint(xr1[k]));
            u64 x2 = splat2(__float_as_uint(xr2[k]));
            u64 x3 = splat2(__float_as_uint(xr3[k]));
            const u64* wrow = (const u64*)&wp0[k * WP2];
            u64 w01 = wrow[0], w23 = wrow[1], w45 = wrow[2];
            fma2(acc[0][0], x0, w01); fma2(acc[0][1], x0, w23); fma2(acc[0][2], x0, w45);
            fma2(acc[1][0], x1, w01); fma2(acc[1][1], x1, w23); fma2(acc[1][2], x1, w45);
            fma2(acc[2][0], x2, w01); fma2(acc[2][1], x2, w23); fma2(acc[2][2], x2, w45);
            fma2(acc[3][0], x3, w01); fma2(acc[3][1], x3, w23); fma2(acc[3][2], x3, w45);
        }

        __syncthreads();

        const int g0 = c * NC + gg * 6;
        #pragma unroll
        for (int p = 0; p < 3; ++p) {
            float b0 = bias[g0 + 2 * p];
            float b1 = bias[g0 + 2 * p + 1];
            #pragma unroll
            for (int i = 0; i < 4; ++i) {
                float2 v = unpack2(acc[i][p]);
                int r = rg * 4 + i;
                ws[r * NC + gg * 6 + 2 * p]     = v.x + b0;
                ws[r * NC + gg * 6 + 2 * p + 1] = v.y + b1;
            }
        }
        __syncthreads();

        #pragma unroll
        for (int v = 0; v < (TM * NC / 4) / 256; ++v) {
            int idx = (v * 256 + tid) * 4;
            int r = idx / NC, col = idx - r * NC;
            float4 val = *(const float4*)&ws[idx];
            *(float4*)&out[(size_t)(rowbase + r) * G3 + c * NC + col] = val;
        }
    }
}

// ---------------------------------------------------------------------------
// Persistent GRU recurrence (R9-exact, best measured: 672 us).
// ---------------------------------------------------------------------------
template <int WRITE_SEQ>
__global__ __launch_bounds__(512, 1)
void gru_recurrent(const float* __restrict__ Whh,
                   const float* __restrict__ bhh)
{
    constexpr int RP = 13;

    extern __shared__ float sm[];
    float* Wn4 = sm;                     // [8][512][4] quad layout
    float* hs  = Wn4 + 8 * 512 * 4;      // [128][4], 16B-aligned
    float* red = hs + HDIM * 4;          // [4][128][RP]

    const int tid = threadIdx.x;
    const int j   = tid & 127;
    const int q   = tid >> 7;
    const int b0  = blockIdx.x * 4;
    const int k0  = q * 32;

    for (int idx = tid; idx < 8 * 512 * 4; idx += 512) {
        int kkg = idx >> 11;
        int rem = idx & 2047;
        int t2  = rem >> 2;
        int m   = rem & 3;
        int j2  = t2 & 127, q2 = t2 >> 7;
        int k2  = q2 * 32 + kkg * 4 + m;
        Wn4[idx] = Whh[(size_t)(2 * HDIM + j2) * HDIM + k2];
    }
    hs[tid & 511] = 0.f;

    unsigned int wrz[64];
    #pragma unroll
    for (int kk = 0; kk < 32; ++kk) {
        wrz[2 * kk]     = __float_as_uint(__ldg(Whh + (size_t)j * HDIM + k0 + kk));
        wrz[2 * kk + 1] = __float_as_uint(__ldg(Whh + (size_t)(HDIM + j) * HDIM + k0 + kk));
    }
    const float bhr = bhh[j];
    const float bhz = bhh[HDIM + j];
    const float bhn = bhh[2 * HDIM + j];

    __syncthreads();

    float* myred = &red[(q * HDIM + j) * RP];
    const float* gi = g_gi + (size_t)(b0 + q) * TDIM * G3;
    const ulonglong2* h16 = (const ulonglong2*)hs;
    const uint4* wn4p = (const uint4*)Wn4 + tid;

    for (int t = 0; t < TDIM; ++t) {
        const float* gip = gi + (size_t)t * G3;
        float ir  = gip[j];
        float iz  = gip[HDIM + j];
        float in_ = gip[2 * HDIM + j];

        u64 a_r01 = 0, a_r23 = 0, a_z01 = 0, a_z23 = 0, a_n01 = 0, a_n23 = 0;

        #pragma unroll
        for (int kkg = 0; kkg < 8; ++kkg) {
            uint4 wq = wn4p[kkg * 512];
            #pragma unroll
            for (int m = 0; m < 4; ++m) {
                int kk = kkg * 4 + m;
                ulonglong2 hv = h16[k0 + kk];
                u64 wr2 = splat2(wrz[2 * kk]);
                u64 wz2 = splat2(wrz[2 * kk + 1]);
                unsigned int wnu = (m == 0) ? wq.x : (m == 1) ? wq.y
                                 : (m == 2) ? wq.z : wq.w;
                u64 wn2 = splat2(wnu);
                fma2(a_r01, wr2, hv.x); fma2(a_r23, wr2, hv.y);
                fma2(a_z01, wz2, hv.x); fma2(a_z23, wz2, hv.y);
                fma2(a_n01, wn2, hv.x); fma2(a_n23, wn2, hv.y);
            }
        }

        {
            float2 v;
            v = unpack2(a_r01); myred[0]  = v.x; myred[1]  = v.y;
            v = unpack2(a_r23); myred[2]  = v.x; myred[3]  = v.y;
            v = unpack2(a_z01); myred[4]  = v.x; myred[5]  = v.y;
            v = unpack2(a_z23); myred[6]  = v.x; myred[7]  = v.y;
            v = unpack2(a_n01); myred[8]  = v.x; myred[9]  = v.y;
            v = unpack2(a_n23); myred[10] = v.x; myred[11] = v.y;
        }
        __syncthreads();

        const int b = q;
        float sr = 0.f, sz = 0.f, sn = 0.f;
        #pragma unroll
        for (int qq = 0; qq < 4; ++qq) {
            const float* rp = &red[(qq * HDIM + j) * RP];
            sr += rp[0 * 4 + b];
            sz += rp[1 * 4 + b];
            sn += rp[2 * 4 + b];
        }
        float r = sigmoid_f(ir + sr + bhr);
        float z = sigmoid_f(iz + sz + bhz);
        float n = tanh_f(in_ + r * (sn + bhn));
        float hold = hs[j * 4 + b];
        float hnew = n + z * (hold - n);

        hs[j * 4 + b] = hnew;
        if (WRITE_SEQ) {
            g_h1[((size_t)(b0 + b) * TDIM + t) * HDIM + j] = hnew;
        } else if (t == TDIM - 1) {
            g_hlast[(size_t)(b0 + b) * HDIM + j] = hnew;
        }
        __syncthreads();
    }
}

// ---------------------------------------------------------------------------
// Final FC (O = 1): one warp per batch.
// ---------------------------------------------------------------------------
__global__ void fc_kernel(const float* __restrict__ Wfc,
                          const float* __restrict__ bfc,
                          float* __restrict__ out)
{
    int w = (blockIdx.x * blockDim.x + threadIdx.x) >> 5;
    int lane = threadIdx.x & 31;
    if (w >= BDIM) return;
    const float* hp = g_hlast + (size_t)w * HDIM;
    float s = 0.f;
    #pragma unroll
    for (int k = lane; k < HDIM; k += 32) s += hp[k] * Wfc[k];
    #pragma unroll
    for (int o = 16; o; o >>= 1) s += __shfl_xor_sync(0xFFFFFFFFu, s, o);
    if (lane == 0) out[w] = s + bfc[0];
}

// ---------------------------------------------------------------------------
extern "C" void kernel_launch(void* const* d_in, const int* in_sizes, int n_in,
                              void* d_out, int out_size)
{
    const float* x     = (const float*)d_in[0];
    const float* W_ih0 = (const float*)d_in[1];
    const float* W_hh0 = (const float*)d_in[2];
    const float* b_ih0 = (const float*)d_in[3];
    const float* b_hh0 = (const float*)d_in[4];
    const float* W_ih1 = (const float*)d_in[5];
    const float* W_hh1 = (const float*)d_in[6];
    const float* b_ih1 = (const float*)d_in[7];
    const float* b_hh1 = (const float*)d_in[8];
    const float* W_fc  = (const float*)d_in[9];
    const float* b_fc  = (const float*)d_in[10];
    float* out = (float*)d_out;

    const int SMEM_G64D = (64 * 132 + 64 * 100) * 4;    // 59,392 B
    const int SMEM_G128 = (64 * 132 + 128 * 100) * 4;   // 85,504 B
    const int SMEM_REC  = (8 * 512 * 4 + HDIM * 4 + 4 * HDIM * 13) * 4; // 94,208 B

    cudaFuncSetAttribute(gi_gemm64_dup, cudaFuncAttributeMaxDynamicSharedMemorySize, SMEM_G64D);
    cudaFuncSetAttribute(gi_gemm<128>,  cudaFuncAttributeMaxDynamicSharedMemorySize, SMEM_G128);
    cudaFuncSetAttribute(gru_recurrent<1>, cudaFuncAttributeMaxDynamicSharedMemorySize, SMEM_REC);
    cudaFuncSetAttribute(gru_recurrent<0>, cudaFuncAttributeMaxDynamicSharedMemorySize, SMEM_REC);

    void* h1ptr = nullptr;
    cudaGetSymbolAddress(&h1ptr, g_h1);
    void* wt0ptr = nullptr;
    cudaGetSymbolAddress(&wt0ptr, g_WT0);
    void* wt1ptr = nullptr;
    cudaGetSymbolAddress(&wt1ptr, g_WT1);

    const int M = BDIM * TDIM;
    const int GEMM_GRID = M / 64;

    transpose_w<64> <<<(G3 * 64  + 255) / 256, 256>>>(W_ih0, (float*)wt0ptr);
    transpose_w<128><<<(G3 * 128 + 255) / 256, 256>>>(W_ih1, (float*)wt1ptr);

    gi_gemm64_dup<<<GEMM_GRID, 256, SMEM_G64D>>>(x, (const float*)wt0ptr, b_ih0);
    gru_recurrent<1><<<BDIM / 4, 512, SMEM_REC>>>(W_hh0, b_hh0);
    gi_gemm<128><<<GEMM_GRID, 256, SMEM_G128>>>((const float*)h1ptr, (const float*)wt1ptr, b_ih1);
    gru_recurrent<0><<<BDIM / 4, 512, SMEM_REC>>>(W_hh1, b_hh1);
    fc_kernel<<<BDIM / 4, 128>>>(W_fc, b_fc, out);
}

// round 15
// speedup vs baseline: 1.1529x; 1.0348x over previous
#include <cuda_runtime.h>
#include <math.h>

#define BDIM 512
#define TDIM 512
#define IN0  64
#define HDIM 128
#define G3   384   // 3*H  (gate order r, z, n)

typedef unsigned long long u64;

// ---------------------------------------------------------------------------
// f32x2 packed helpers
// ---------------------------------------------------------------------------
__device__ __forceinline__ u64 splat2(unsigned int v) {
    u64 r; asm("mov.b64 %0, {%1, %1};" : "=l"(r) : "r"(v)); return r;
}
__device__ __forceinline__ void fma2(u64& d, u64 a, u64 b) {
    asm("fma.rn.f32x2 %0, %1, %2, %0;" : "+l"(d) : "l"(a), "l"(b));
}
__device__ __forceinline__ float2 unpack2(u64 v) {
    unsigned int lo, hi;
    asm("mov.b64 {%0, %1}, %2;" : "=r"(lo), "=r"(hi) : "l"(v));
    float2 f; f.x = __uint_as_float(lo); f.y = __uint_as_float(hi); return f;
}
__device__ __forceinline__ float sigmoid_f(float x) {
    return __fdividef(1.f, 1.f + __expf(-x));
}
__device__ __forceinline__ float tanh_f(float x) {
    // 2*sigmoid(2x) - 1 : short MUFU chain, rel err ~1e-6 (validated)
    return __fmaf_rn(2.f, __fdividef(1.f, 1.f + __expf(-2.f * x)), -1.f);
}

// ---------------------------------------------------------------------------
// Scratch
// ---------------------------------------------------------------------------
__device__ float g_gi [(size_t)BDIM * TDIM * G3];
__device__ float g_h1 [(size_t)BDIM * TDIM * HDIM];
__device__ float g_hlast[(size_t)BDIM * HDIM];
__device__ float g_WT0[64  * G3];    // W_ih0 transposed: [K][384]
__device__ float g_WT1[128 * G3];    // W_ih1 transposed: [K][384]

// ---------------------------------------------------------------------------
// One-time W_ih transpose: WT[k][g] = W[g][k].
// ---------------------------------------------------------------------------
template <int K>
__global__ void transpose_w(const float* __restrict__ W, float* __restrict__ WT)
{
    int idx = blockIdx.x * blockDim.x + threadIdx.x;
    if (idx >= G3 * K) return;
    int g = idx / K, k = idx - g * K;
    WT[k * G3 + g] = W[idx];
}

// ---------------------------------------------------------------------------
// gi GEMM K=64 (R9-exact, 43 KB smem -> 5 CTAs/SM).
// ---------------------------------------------------------------------------
__global__ __launch_bounds__(256)
void gi_gemm64(const float* __restrict__ X,
               const float* __restrict__ WT,   // [64][384] transposed
               const float* __restrict__ bias)
{
    constexpr int K   = 64;
    constexpr int TM  = 64;
    constexpr int NC  = 96;
    constexpr int XP  = K + 4;
    constexpr int WP2 = 100;

    extern __shared__ float sm[];
    float* xs = sm;               // [TM][XP] row-major
    float* ws = sm + TM * XP;     // [K][WP2]; reused as [64][96] staging

    const int tid = threadIdx.x;
    const int rowbase = blockIdx.x * TM;

    for (int idx = tid; idx < TM * (K / 4); idx += 256) {
        int r = idx / (K / 4), kb = idx - r * (K / 4);
        float4 v = *(const float4*)&X[(size_t)(rowbase + r) * K + kb * 4];
        *(float4*)&xs[r * XP + kb * 4] = v;
    }

    const int rg = tid >> 4;
    const int gg = tid & 15;
    float* out = g_gi;

    for (int c = 0; c < 4; ++c) {
        __syncthreads();
        for (int idx = tid; idx < K * (NC / 4); idx += 256) {
            int k = idx / (NC / 4), g4 = idx - k * (NC / 4);
            float4 v = *(const float4*)&WT[(size_t)k * G3 + c * NC + g4 * 4];
            *(float4*)&ws[k * WP2 + g4 * 4] = v;
        }
        __syncthreads();

        u64 acc[4][3];
        #pragma unroll
        for (int i = 0; i < 4; ++i)
            #pragma unroll
            for (int p = 0; p < 3; ++p) acc[i][p] = 0ull;

        const float* xr0 = &xs[(rg * 4 + 0) * XP];
        const float* xr1 = &xs[(rg * 4 + 1) * XP];
        const float* xr2 = &xs[(rg * 4 + 2) * XP];
        const float* xr3 = &xs[(rg * 4 + 3) * XP];
        const float* wp0 = &ws[gg * 6];

        #pragma unroll 4
        for (int k = 0; k < K; ++k) {
            u64 x0 = splat2(__float_as_uint(xr0[k]));
            u64 x1 = splat2(__float_as_uint(xr1[k]));
            u64 x2 = splat2(__float_as_uint(xr2[k]));
            u64 x3 = splat2(__float_as_uint(xr3[k]));
            const u64* wrow = (const u64*)&wp0[k * WP2];
            u64 w01 = wrow[0], w23 = wrow[1], w45 = wrow[2];
            fma2(acc[0][0], x0, w01); fma2(acc[0][1], x0, w23); fma2(acc[0][2], x0, w45);
            fma2(acc[1][0], x1, w01); fma2(acc[1][1], x1, w23); fma2(acc[1][2], x1, w45);
            fma2(acc[2][0], x2, w01); fma2(acc[2][1], x2, w23); fma2(acc[2][2], x2, w45);
            fma2(acc[3][0], x3, w01); fma2(acc[3][1], x3, w23); fma2(acc[3][2], x3, w45);
        }

        __syncthreads();

        const int g0 = c * NC + gg * 6;
        #pragma unroll
        for (int p = 0; p < 3; ++p) {
            float b0 = bias[g0 + 2 * p];
            float b1 = bias[g0 + 2 * p + 1];
            #pragma unroll
            for (int i = 0; i < 4; ++i) {
                float2 v = unpack2(acc[i][p]);
                int r = rg * 4 + i;
                ws[r * NC + gg * 6 + 2 * p]     = v.x + b0;
                ws[r * NC + gg * 6 + 2 * p + 1] = v.y + b1;
            }
        }
        __syncthreads();

        #pragma unroll
        for (int v = 0; v < (TM * NC / 4) / 256; ++v) {
            int idx = (v * 256 + tid) * 4;
            int r = idx / NC, col = idx - r * NC;
            float4 val = *(const float4*)&ws[idx];
            *(float4*)&out[(size_t)(rowbase + r) * G3 + c * NC + col] = val;
        }
    }
}

// ---------------------------------------------------------------------------
// gi GEMM K=128, v15: R9 inner loop, xs staged ONCE (full K), ws staged in
// two 64-k halves -> smem 85.5 KB -> 59.4 KB -> 3 CTAs/SM (was 2).
// Accumulators persist across halves in registers.
// ---------------------------------------------------------------------------
__global__ __launch_bounds__(256)
void gi_gemm128(const float* __restrict__ X,
                const float* __restrict__ WT,   // [128][384] transposed
                const float* __restrict__ bias)
{
    constexpr int K   = 128;
    constexpr int KT  = 64;          // W staging tile
    constexpr int TM  = 64;
    constexpr int NC  = 96;
    constexpr int XP  = K + 4;       // 132
    constexpr int WP2 = 100;

    extern __shared__ float sm[];
    float* xs = sm;               // [TM][132] row-major, staged once
    float* ws = sm + TM * XP;     // [KT][WP2]; reused as [64][96] staging

    const int tid = threadIdx.x;
    const int rowbase = blockIdx.x * TM;

    // Stage full X tile once (float4 in/out).
    for (int idx = tid; idx < TM * (K / 4); idx += 256) {
        int r = idx / (K / 4), kb = idx - r * (K / 4);
        float4 v = *(const float4*)&X[(size_t)(rowbase + r) * K + kb * 4];
        *(float4*)&xs[r * XP + kb * 4] = v;
    }

    const int rg = tid >> 4;
    const int gg = tid & 15;
    float* out = g_gi;

    for (int c = 0; c < 4; ++c) {
        u64 acc[4][3];
        #pragma unroll
        for (int i = 0; i < 4; ++i)
            #pragma unroll
            for (int p = 0; p < 3; ++p) acc[i][p] = 0ull;

        const float* xr0 = &xs[(rg * 4 + 0) * XP];
        const float* xr1 = &xs[(rg * 4 + 1) * XP];
        const float* xr2 = &xs[(rg * 4 + 2) * XP];
        const float* xr3 = &xs[(rg * 4 + 3) * XP];
        const float* wp0 = &ws[gg * 6];

        #pragma unroll
        for (int hh = 0; hh < 2; ++hh) {
            __syncthreads();   // previous readers of ws done
            // Stage W half: coalesced float4.
            for (int idx = tid; idx < KT * (NC / 4); idx += 256) {
                int k = idx / (NC / 4), g4 = idx - k * (NC / 4);
                float4 v = *(const float4*)&WT[(size_t)(hh * KT + k) * G3 + c * NC + g4 * 4];
                *(float4*)&ws[k * WP2 + g4 * 4] = v;
            }
            __syncthreads();

            const int kb = hh * KT;
            #pragma unroll 4
            for (int k = 0; k < KT; ++k) {
                u64 x0 = splat2(__float_as_uint(xr0[kb + k]));
                u64 x1 = splat2(__float_as_uint(xr1[kb + k]));
                u64 x2 = splat2(__float_as_uint(xr2[kb + k]));
                u64 x3 = splat2(__float_as_uint(xr3[kb + k]));
                const u64* wrow = (const u64*)&wp0[k * WP2];
                u64 w01 = wrow[0], w23 = wrow[1], w45 = wrow[2];
                fma2(acc[0][0], x0, w01); fma2(acc[0][1], x0, w23); fma2(acc[0][2], x0, w45);
                fma2(acc[1][0], x1, w01); fma2(acc[1][1], x1, w23); fma2(acc[1][2], x1, w45);
                fma2(acc[2][0], x2, w01); fma2(acc[2][1], x2, w23); fma2(acc[2][2], x2, w45);
                fma2(acc[3][0], x3, w01); fma2(acc[3][1], x3, w23); fma2(acc[3][2], x3, w45);
            }
        }

        __syncthreads();  // done reading ws; reuse as output staging

        const int g0 = c * NC + gg * 6;
        #pragma unroll
        for (int p = 0; p < 3; ++p) {
            float b0 = bias[g0 + 2 * p];
            float b1 = bias[g0 + 2 * p + 1];
            #pragma unroll
            for (int i = 0; i < 4; ++i) {
                float2 v = unpack2(acc[i][p]);
                int r = rg * 4 + i;
                ws[r * NC + gg * 6 + 2 * p]     = v.x + b0;
                ws[r * NC + gg * 6 + 2 * p + 1] = v.y + b1;
            }
        }
        __syncthreads();

        #pragma unroll
        for (int v = 0; v < (TM * NC / 4) / 256; ++v) {
            int idx = (v * 256 + tid) * 4;
            int r = idx / NC, col = idx - r * NC;
            float4 val = *(const float4*)&ws[idx];
            *(float4*)&out[(size_t)(rowbase + r) * G3 + c * NC + col] = val;
        }
    }
}

// ---------------------------------------------------------------------------
// Persistent GRU recurrence (R9-exact, best measured: 672 us).
// ---------------------------------------------------------------------------
template <int WRITE_SEQ>
__global__ __launch_bounds__(512, 1)
void gru_recurrent(const float* __restrict__ Whh,
                   const float* __restrict__ bhh)
{
    constexpr int RP = 13;

    extern __shared__ float sm[];
    float* Wn4 = sm;                     // [8][512][4] quad layout
    float* hs  = Wn4 + 8 * 512 * 4;      // [128][4], 16B-aligned
    float* red = hs + HDIM * 4;          // [4][128][RP]

    const int tid = threadIdx.x;
    const int j   = tid & 127;
    const int q   = tid >> 7;
    const int b0  = blockIdx.x * 4;
    const int k0  = q * 32;

    for (int idx = tid; idx < 8 * 512 * 4; idx += 512) {
        int kkg = idx >> 11;
        int rem = idx & 2047;
        int t2  = rem >> 2;
        int m   = rem & 3;
        int j2  = t2 & 127, q2 = t2 >> 7;
        int k2  = q2 * 32 + kkg * 4 + m;
        Wn4[idx] = Whh[(size_t)(2 * HDIM + j2) * HDIM + k2];
    }
    hs[tid & 511] = 0.f;

    unsigned int wrz[64];
    #pragma unroll
    for (int kk = 0; kk < 32; ++kk) {
        wrz[2 * kk]     = __float_as_uint(__ldg(Whh + (size_t)j * HDIM + k0 + kk));
        wrz[2 * kk + 1] = __float_as_uint(__ldg(Whh + (size_t)(HDIM + j) * HDIM + k0 + kk));
    }
    const float bhr = bhh[j];
    const float bhz = bhh[HDIM + j];
    const float bhn = bhh[2 * HDIM + j];

    __syncthreads();

    float* myred = &red[(q * HDIM + j) * RP];
    const float* gi = g_gi + (size_t)(b0 + q) * TDIM * G3;
    const ulonglong2* h16 = (const ulonglong2*)hs;
    const uint4* wn4p = (const uint4*)Wn4 + tid;

    for (int t = 0; t < TDIM; ++t) {
        const float* gip = gi + (size_t)t * G3;
        float ir  = gip[j];
        float iz  = gip[HDIM + j];
        float in_ = gip[2 * HDIM + j];

        u64 a_r01 = 0, a_r23 = 0, a_z01 = 0, a_z23 = 0, a_n01 = 0, a_n23 = 0;

        #pragma unroll
        for (int kkg = 0; kkg < 8; ++kkg) {
            uint4 wq = wn4p[kkg * 512];
            #pragma unroll
            for (int m = 0; m < 4; ++m) {
                int kk = kkg * 4 + m;
                ulonglong2 hv = h16[k0 + kk];
                u64 wr2 = splat2(wrz[2 * kk]);
                u64 wz2 = splat2(wrz[2 * kk + 1]);
                unsigned int wnu = (m == 0) ? wq.x : (m == 1) ? wq.y
                                 : (m == 2) ? wq.z : wq.w;
                u64 wn2 = splat2(wnu);
                fma2(a_r01, wr2, hv.x); fma2(a_r23, wr2, hv.y);
                fma2(a_z01, wz2, hv.x); fma2(a_z23, wz2, hv.y);
                fma2(a_n01, wn2, hv.x); fma2(a_n23, wn2, hv.y);
            }
        }

        {
            float2 v;
            v = unpack2(a_r01); myred[0]  = v.x; myred[1]  = v.y;
            v = unpack2(a_r23); myred[2]  = v.x; myred[3]  = v.y;
            v = unpack2(a_z01); myred[4]  = v.x; myred[5]  = v.y;
            v = unpack2(a_z23); myred[6]  = v.x; myred[7]  = v.y;
            v = unpack2(a_n01); myred[8]  = v.x; myred[9]  = v.y;
            v = unpack2(a_n23); myred[10] = v.x; myred[11] = v.y;
        }
        __syncthreads();

        const int b = q;
        float sr = 0.f, sz = 0.f, sn = 0.f;
        #pragma unroll
        for (int qq = 0; qq < 4; ++qq) {
            const float* rp = &red[(qq * HDIM + j) * RP];
            sr += rp[0 * 4 + b];
            sz += rp[1 * 4 + b];
            sn += rp[2 * 4 + b];
        }
        float r = sigmoid_f(ir + sr + bhr);
        float z = sigmoid_f(iz + sz + bhz);
        float n = tanh_f(in_ + r * (sn + bhn));
        float hold = hs[j * 4 + b];
        float hnew = n + z * (hold - n);

        hs[j * 4 + b] = hnew;
        if (WRITE_SEQ) {
            g_h1[((size_t)(b0 + b) * TDIM + t) * HDIM + j] = hnew;
        } else if (t == TDIM - 1) {
            g_hlast[(size_t)(b0 + b) * HDIM + j] = hnew;
        }
        __syncthreads();
    }
}

// ---------------------------------------------------------------------------
// Final FC (O = 1): one warp per batch.
// ---------------------------------------------------------------------------
__global__ void fc_kernel(const float* __restrict__ Wfc,
                          const float* __restrict__ bfc,
                          float* __restrict__ out)
{
    int w = (blockIdx.x * blockDim.x + threadIdx.x) >> 5;
    int lane = threadIdx.x & 31;
    if (w >= BDIM) return;
    const float* hp = g_hlast + (size_t)w * HDIM;
    float s = 0.f;
    #pragma unroll
    for (int k = lane; k < HDIM; k += 32) s += hp[k] * Wfc[k];
    #pragma unroll
    for (int o = 16; o; o >>= 1) s += __shfl_xor_sync(0xFFFFFFFFu, s, o);
    if (lane == 0) out[w] = s + bfc[0];
}

// ---------------------------------------------------------------------------
extern "C" void kernel_launch(void* const* d_in, const int* in_sizes, int n_in,
                              void* d_out, int out_size)
{
    const float* x     = (const float*)d_in[0];
    const float* W_ih0 = (const float*)d_in[1];
    const float* W_hh0 = (const float*)d_in[2];
    const float* b_ih0 = (const float*)d_in[3];
    const float* b_hh0 = (const float*)d_in[4];
    const float* W_ih1 = (const float*)d_in[5];
    const float* W_hh1 = (const float*)d_in[6];
    const float* b_ih1 = (const float*)d_in[7];
    const float* b_hh1 = (const float*)d_in[8];
    const float* W_fc  = (const float*)d_in[9];
    const float* b_fc  = (const float*)d_in[10];
    float* out = (float*)d_out;

    const int SMEM_G64  = (64 * 68  + 64 * 100) * 4;    // 43,008 B -> 5 CTAs
    const int SMEM_G128 = (64 * 132 + 64 * 100) * 4;    // 59,392 B -> 3 CTAs
    const int SMEM_REC  = (8 * 512 * 4 + HDIM * 4 + 4 * HDIM * 13) * 4; // 94,208 B

    cudaFuncSetAttribute(gi_gemm64,  cudaFuncAttributeMaxDynamicSharedMemorySize, SMEM_G64);
    cudaFuncSetAttribute(gi_gemm128, cudaFuncAttributeMaxDynamicSharedMemorySize, SMEM_G128);
    cudaFuncSetAttribute(gru_recurrent<1>, cudaFuncAttributeMaxDynamicSharedMemorySize, SMEM_REC);
    cudaFuncSetAttribute(gru_recurrent<0>, cudaFuncAttributeMaxDynamicSharedMemorySize, SMEM_REC);

    void* h1ptr = nullptr;
    cudaGetSymbolAddress(&h1ptr, g_h1);
    void* wt0ptr = nullptr;
    cudaGetSymbolAddress(&wt0ptr, g_WT0);
    void* wt1ptr = nullptr;
    cudaGetSymbolAddress(&wt1ptr, g_WT1);

    const int M = BDIM * TDIM;
    const int GEMM_GRID = M / 64;

    transpose_w<64> <<<(G3 * 64  + 255) / 256, 256>>>(W_ih0, (float*)wt0ptr);
    transpose_w<128><<<(G3 * 128 + 255) / 256, 256>>>(W_ih1, (float*)wt1ptr);

    gi_gemm64<<<GEMM_GRID, 256, SMEM_G64>>>(x, (const float*)wt0ptr, b_ih0);
    gru_recurrent<1><<<BDIM / 4, 512, SMEM_REC>>>(W_hh0, b_hh0);
    gi_gemm128<<<GEMM_GRID, 256, SMEM_G128>>>((const float*)h1ptr, (const float*)wt1ptr, b_ih1);
    gru_recurrent<0><<<BDIM / 4, 512, SMEM_REC>>>(W_hh1, b_hh1);
    fc_kernel<<<BDIM / 4, 128>>>(W_fc, b_fc, out);
}